// round 2
// baseline (speedup 1.0000x reference)
#include <cuda_runtime.h>

#define NPIX 4096
#define CIN  512
#define B    4

// Scratch (device globals — allocation-free per harness rules)
__device__ float g_qk[(size_t)B * 128 * NPIX];            // q rows 0-63, k rows 64-127
__device__ float g_v[(size_t)B * CIN * NPIX];             // 32 MB
__device__ float g_attn[(size_t)B * NPIX * NPIX];         // 256 MB

// ---------------------------------------------------------------------------
// proj: y[b, row_off+o, n] = sum_c W[o,c] * x[b,c,n] + bias[o]
// Tiles: 64(o) x 64(n), K-step 16. 256 threads, 4x4 per thread.
// ---------------------------------------------------------------------------
__global__ __launch_bounds__(256)
void proj_kernel(const float* __restrict__ W, const float* __restrict__ bias,
                 const float* __restrict__ x, float* __restrict__ y,
                 int ybatch, int row_off)
{
    __shared__ float Ws[64][16];     // [o][k]
    __shared__ float Xs[16][64];     // [k][n]
    const int b  = blockIdx.z;
    const int n0 = blockIdx.x * 64;
    const int o0 = blockIdx.y * 64;
    const int tid = threadIdx.x;
    const int tx = tid & 15;         // n / 4
    const int ty = tid >> 4;         // o / 4
    float acc[4][4] = {};
    const float* xb = x + (size_t)b * CIN * NPIX;

    for (int c0 = 0; c0 < CIN; c0 += 16) {
        int idx = tid;
        #pragma unroll
        for (int t = 0; t < 4; t++) {            // 64x16 W tile
            int r = idx >> 4, k = idx & 15;
            Ws[r][k] = W[(size_t)(o0 + r) * CIN + c0 + k];
            idx += 256;
        }
        idx = tid;
        #pragma unroll
        for (int t = 0; t < 4; t++) {            // 16x64 x tile (coalesced in n)
            int k = idx >> 6, nn = idx & 63;
            Xs[k][nn] = xb[(size_t)(c0 + k) * NPIX + n0 + nn];
            idx += 256;
        }
        __syncthreads();
        #pragma unroll
        for (int kk = 0; kk < 16; kk++) {
            float xv[4], wv[4];
            #pragma unroll
            for (int j = 0; j < 4; j++) xv[j] = Xs[kk][tx * 4 + j];
            #pragma unroll
            for (int i = 0; i < 4; i++) wv[i] = Ws[ty * 4 + i][kk];
            #pragma unroll
            for (int i = 0; i < 4; i++)
                #pragma unroll
                for (int j = 0; j < 4; j++)
                    acc[i][j] += wv[i] * xv[j];
        }
        __syncthreads();
    }

    float* yb = y + (size_t)b * ybatch + (size_t)row_off * NPIX;
    #pragma unroll
    for (int i = 0; i < 4; i++) {
        float bo = bias[o0 + ty * 4 + i];
        #pragma unroll
        for (int j = 0; j < 4; j++)
            yb[(size_t)(o0 + ty * 4 + i) * NPIX + n0 + tx * 4 + j] = acc[i][j] + bo;
    }
}

// ---------------------------------------------------------------------------
// scores: S[b,m,n] = sum_d q[b,d,m] * k[b,d,n]   (K = 64, one shot)
// Tiles: 64(m) x 64(n). 256 threads, 4x4 per thread.
// ---------------------------------------------------------------------------
__global__ __launch_bounds__(256)
void scores_kernel()
{
    __shared__ float Qs[64][64];     // [d][m]
    __shared__ float Ks[64][64];     // [d][n]
    const int b  = blockIdx.z;
    const int n0 = blockIdx.x * 64;
    const int m0 = blockIdx.y * 64;
    const int tid = threadIdx.x;
    const int tx = tid & 15;         // n / 4
    const int ty = tid >> 4;         // m / 4
    const float* q = g_qk + (size_t)b * 128 * NPIX;
    const float* k = q + (size_t)64 * NPIX;

    int idx = tid;
    #pragma unroll
    for (int t = 0; t < 16; t++) {               // 64x64 tiles, coalesced
        int d = idx >> 6, c = idx & 63;
        Qs[d][c] = q[(size_t)d * NPIX + m0 + c];
        Ks[d][c] = k[(size_t)d * NPIX + n0 + c];
        idx += 256;
    }
    __syncthreads();

    float acc[4][4] = {};
    #pragma unroll 16
    for (int d = 0; d < 64; d++) {
        float qv[4], kv[4];
        #pragma unroll
        for (int i = 0; i < 4; i++) qv[i] = Qs[d][ty * 4 + i];
        #pragma unroll
        for (int j = 0; j < 4; j++) kv[j] = Ks[d][tx * 4 + j];
        #pragma unroll
        for (int i = 0; i < 4; i++)
            #pragma unroll
            for (int j = 0; j < 4; j++)
                acc[i][j] += qv[i] * kv[j];
    }

    float* S = g_attn + ((size_t)b * NPIX + m0) * NPIX + n0;
    #pragma unroll
    for (int i = 0; i < 4; i++)
        #pragma unroll
        for (int j = 0; j < 4; j++)
            S[(size_t)(ty * 4 + i) * NPIX + tx * 4 + j] = acc[i][j];
}

// ---------------------------------------------------------------------------
// softmax over last axis, in place. One CTA per row, 16 elems/thread in regs.
// ---------------------------------------------------------------------------
__global__ __launch_bounds__(256)
void softmax_kernel()
{
    __shared__ float red[256];
    const int m = blockIdx.x, b = blockIdx.y;
    float* p = g_attn + ((size_t)b * NPIX + m) * NPIX;
    const int tid = threadIdx.x;

    float r[16];
    float mx = -1e30f;
    #pragma unroll
    for (int t = 0; t < 16; t++) {
        r[t] = p[tid + t * 256];
        mx = fmaxf(mx, r[t]);
    }
    red[tid] = mx;
    __syncthreads();
    for (int s = 128; s > 0; s >>= 1) {
        if (tid < s) red[tid] = fmaxf(red[tid], red[tid + s]);
        __syncthreads();
    }
    mx = red[0];
    __syncthreads();

    float sum = 0.f;
    #pragma unroll
    for (int t = 0; t < 16; t++) {
        r[t] = __expf(r[t] - mx);
        sum += r[t];
    }
    red[tid] = sum;
    __syncthreads();
    for (int s = 128; s > 0; s >>= 1) {
        if (tid < s) red[tid] += red[tid + s];
        __syncthreads();
    }
    float inv = 1.0f / red[0];

    #pragma unroll
    for (int t = 0; t < 16; t++)
        p[tid + t * 256] = r[t] * inv;
}

// ---------------------------------------------------------------------------
// out[b,c,m] = sum_n v[b,c,n] * attn[b,m,n] + x[b,c,m]
// Tiles: 64(c) x 64(m), K-step 32 over n. 256 threads, 4x4 per thread.
// ---------------------------------------------------------------------------
__global__ __launch_bounds__(256)
void out_kernel(const float* __restrict__ x, float* __restrict__ out)
{
    __shared__ float Vs[64][32];     // [c][n]
    __shared__ float As[32][65];     // [n][m]  (pad to keep writes conflict-free)
    const int b  = blockIdx.z;
    const int m0 = blockIdx.x * 64;
    const int c0 = blockIdx.y * 64;
    const int tid = threadIdx.x;
    const int tx = tid & 15;         // m / 4
    const int ty = tid >> 4;         // c / 4
    float acc[4][4] = {};
    const float* vb = g_v    + (size_t)b * CIN * NPIX;
    const float* ab = g_attn + (size_t)b * NPIX * NPIX;

    for (int n0 = 0; n0 < NPIX; n0 += 32) {
        int idx = tid;
        #pragma unroll
        for (int t = 0; t < 8; t++) {            // 64x32 v tile (coalesced in n)
            int cc = idx >> 5, kk2 = idx & 31;
            Vs[cc][kk2] = vb[(size_t)(c0 + cc) * NPIX + n0 + kk2];
            idx += 256;
        }
        idx = tid;
        #pragma unroll
        for (int t = 0; t < 8; t++) {            // 64x32 attn tile, transposed into [n][m]
            int mm = idx >> 5, kk2 = idx & 31;
            As[kk2][mm] = ab[(size_t)(m0 + mm) * NPIX + n0 + kk2];
            idx += 256;
        }
        __syncthreads();
        #pragma unroll
        for (int kk = 0; kk < 32; kk++) {
            float vv[4], av[4];
            #pragma unroll
            for (int i = 0; i < 4; i++) vv[i] = Vs[ty * 4 + i][kk];
            #pragma unroll
            for (int j = 0; j < 4; j++) av[j] = As[kk][tx * 4 + j];
            #pragma unroll
            for (int i = 0; i < 4; i++)
                #pragma unroll
                for (int j = 0; j < 4; j++)
                    acc[i][j] += vv[i] * av[j];
        }
        __syncthreads();
    }

    const float* xb = x + (size_t)b * CIN * NPIX;
    float* ob = out + (size_t)b * CIN * NPIX;
    #pragma unroll
    for (int i = 0; i < 4; i++)
        #pragma unroll
        for (int j = 0; j < 4; j++) {
            size_t off = (size_t)(c0 + ty * 4 + i) * NPIX + m0 + tx * 4 + j;
            ob[off] = acc[i][j] + xb[off];
        }
}

// ---------------------------------------------------------------------------
extern "C" void kernel_launch(void* const* d_in, const int* in_sizes, int n_in,
                              void* d_out, int out_size)
{
    const float* x  = (const float*)d_in[0];
    const float* Wq = (const float*)d_in[1];
    const float* bq = (const float*)d_in[2];
    const float* Wk = (const float*)d_in[3];
    const float* bk = (const float*)d_in[4];
    const float* Wv = (const float*)d_in[5];
    const float* bv = (const float*)d_in[6];
    float* out = (float*)d_out;

    float *qk, *v;
    cudaGetSymbolAddress((void**)&qk, g_qk);
    cudaGetSymbolAddress((void**)&v,  g_v);

    dim3 blk(256);
    proj_kernel<<<dim3(NPIX / 64, 1, B), blk>>>(Wq, bq, x, qk, 128 * NPIX, 0);
    proj_kernel<<<dim3(NPIX / 64, 1, B), blk>>>(Wk, bk, x, qk, 128 * NPIX, 64);
    proj_kernel<<<dim3(NPIX / 64, CIN / 64, B), blk>>>(Wv, bv, x, v, CIN * NPIX, 0);
    scores_kernel<<<dim3(NPIX / 64, NPIX / 64, B), blk>>>();
    softmax_kernel<<<dim3(NPIX, B), blk>>>();
    out_kernel<<<dim3(NPIX / 64, CIN / 64, B), blk>>>(x, out);
}

// round 4
// speedup vs baseline: 7.8285x; 7.8285x over previous
#include <cuda_runtime.h>
#include <cuda_bf16.h>
#include <cstdint>

#define NPIX 4096
#define CIN  512
#define B    4

__device__ __align__(16) __nv_bfloat16 g_xT[(size_t)B * NPIX * CIN];   // [b][n][c]
__device__ __align__(16) __nv_bfloat16 g_q [(size_t)B * NPIX * 64];    // [b][n][d]
__device__ __align__(16) __nv_bfloat16 g_k [(size_t)B * NPIX * 64];    // [b][n][d]
__device__ __align__(16) __nv_bfloat16 g_v [(size_t)B * NPIX * CIN];   // [b][n][c]
__device__ __align__(16) __nv_bfloat16 g_wqk[128 * CIN];               // [q64;k64][c]
__device__ __align__(16) __nv_bfloat16 g_wv [CIN * CIN];               // [o][c]

// ------------------------------ helpers -----------------------------------
__device__ __forceinline__ uint32_t smem_u32(const void* p) {
    uint32_t a;
    asm("{ .reg .u64 t; cvta.to.shared.u64 t, %1; cvt.u32.u64 %0, t; }" : "=r"(a) : "l"(p));
    return a;
}
__device__ __forceinline__ void ldsm_x4(uint32_t* r, uint32_t a) {
    asm volatile("ldmatrix.sync.aligned.m8n8.x4.shared.b16 {%0,%1,%2,%3}, [%4];"
        : "=r"(r[0]), "=r"(r[1]), "=r"(r[2]), "=r"(r[3]) : "r"(a));
}
__device__ __forceinline__ void ldsm_x4t(uint32_t* r, uint32_t a) {
    asm volatile("ldmatrix.sync.aligned.m8n8.x4.trans.shared.b16 {%0,%1,%2,%3}, [%4];"
        : "=r"(r[0]), "=r"(r[1]), "=r"(r[2]), "=r"(r[3]) : "r"(a));
}
__device__ __forceinline__ void mma_bf16(float* d, const uint32_t* a, const uint32_t* b) {
    asm volatile("mma.sync.aligned.m16n8k16.row.col.f32.bf16.bf16.f32 "
        "{%0,%1,%2,%3},{%4,%5,%6,%7},{%8,%9},{%0,%1,%2,%3};"
        : "+f"(d[0]), "+f"(d[1]), "+f"(d[2]), "+f"(d[3])
        : "r"(a[0]), "r"(a[1]), "r"(a[2]), "r"(a[3]), "r"(b[0]), "r"(b[1]));
}
__device__ __forceinline__ void cp16(uint32_t dst, const void* src) {
    asm volatile("cp.async.cg.shared.global [%0], [%1], 16;" :: "r"(dst), "l"(src));
}
#define CP_COMMIT() asm volatile("cp.async.commit_group;" ::: "memory")
#define CP_WAIT0()  asm volatile("cp.async.wait_group 0;" ::: "memory")
__device__ __forceinline__ uint32_t pack_bf2(float lo, float hi) {
    uint32_t u;
    asm("cvt.rn.bf16x2.f32 %0, %1, %2;" : "=r"(u) : "f"(hi), "f"(lo));  // hi->upper, lo->lower
    return u;
}

// -------------------------- prep kernels ----------------------------------
__global__ void convert_w_kernel(const float* __restrict__ Wq, const float* __restrict__ Wk,
                                 const float* __restrict__ Wv) {
    int i = blockIdx.x * 256 + threadIdx.x;
    if (i < 64 * CIN) g_wqk[i] = __float2bfloat16(Wq[i]);
    else if (i < 128 * CIN) g_wqk[i] = __float2bfloat16(Wk[i - 64 * CIN]);
    else if (i < 128 * CIN + CIN * CIN) g_wv[i - 128 * CIN] = __float2bfloat16(Wv[i - 128 * CIN]);
}

__global__ __launch_bounds__(256)
void transpose_x_kernel(const float* __restrict__ x) {
    __shared__ float s[64][65];
    const int n0 = blockIdx.x * 64, c0 = blockIdx.y * 64, b = blockIdx.z;
    const float* xb = x + ((size_t)b * CIN + c0) * NPIX + n0;
    for (int i = threadIdx.x; i < 64 * 64; i += 256) {
        int c = i >> 6, n = i & 63;
        s[c][n] = xb[(size_t)c * NPIX + n];
    }
    __syncthreads();
    __nv_bfloat16* dst = g_xT + ((size_t)b * NPIX + n0) * CIN + c0;
    for (int i = threadIdx.x; i < 64 * 32; i += 256) {
        int n = i >> 5, c2 = (i & 31) * 2;
        *reinterpret_cast<__nv_bfloat162*>(dst + (size_t)n * CIN + c2) =
            __float22bfloat162_rn(make_float2(s[c2][n], s[c2 + 1][n]));
    }
}

// ---------------- proj_qk: C[n(128), q64|k64] = xT . Wqk^T ----------------
// smem: A 2x(128x72 bf16)=36864, B 2x(128x72)=36864 ; rows padded to 144B
__global__ __launch_bounds__(256)
void proj_qk_kernel(const float* __restrict__ bq, const float* __restrict__ bk) {
    extern __shared__ char dsm[];
    const uint32_t sb = smem_u32(dsm);
    const uint32_t SA = sb, SB = sb + 36864;
    const int tid = threadIdx.x, wid = tid >> 5, lane = tid & 31;
    const int n0 = blockIdx.x * 128, b = blockIdx.y;
    const __nv_bfloat16* gA = g_xT + ((size_t)b * NPIX + n0) * CIN;

    auto ldA = [&](uint32_t dst, int kk) {
        for (int i = tid; i < 1024; i += 256) {
            int r = i >> 3, s = i & 7;
            cp16(dst + r * 144 + s * 16, gA + (size_t)r * CIN + kk * 64 + s * 8);
        }
    };
    auto ldB = [&](uint32_t dst, int kk) {
        for (int i = tid; i < 1024; i += 256) {
            int r = i >> 3, s = i & 7;
            cp16(dst + r * 144 + s * 16, g_wqk + (size_t)r * CIN + kk * 64 + s * 8);
        }
    };
    ldA(SA, 0); ldB(SB, 0); CP_COMMIT(); CP_WAIT0(); __syncthreads();

    const int ar = (lane & 7) + ((lane >> 3) & 1) * 8, ak = ((lane >> 4) & 1) * 8;
    const int bn = ((lane >> 4) & 1) * 8 + (lane & 7), bk2 = ((lane >> 3) & 1) * 8;
    float o[16][4] = {};

    for (int kk = 0; kk < 8; kk++) {
        const int buf = kk & 1;
        if (kk < 7) { ldA(SA + (buf ^ 1) * 18432, kk + 1); ldB(SB + (buf ^ 1) * 18432, kk + 1); CP_COMMIT(); }
        const uint32_t Ab = SA + buf * 18432 + (16 * wid + ar) * 144 + ak * 2;
        const uint32_t Bb = SB + buf * 18432;
        uint32_t qa[4][4];
        #pragma unroll
        for (int kc = 0; kc < 4; kc++) ldsm_x4(qa[kc], Ab + kc * 32);
        #pragma unroll
        for (int ot2 = 0; ot2 < 8; ot2++) {
            #pragma unroll
            for (int kc = 0; kc < 4; kc++) {
                uint32_t br[4];
                ldsm_x4(br, Bb + (ot2 * 16 + bn) * 144 + (kc * 16 + bk2) * 2);
                mma_bf16(o[ot2 * 2],     qa[kc], br);
                mma_bf16(o[ot2 * 2 + 1], qa[kc], br + 2);
            }
        }
        if (kk < 7) CP_WAIT0();
        __syncthreads();
    }

    const int r0 = 16 * wid + (lane >> 2);
    #pragma unroll
    for (int ot = 0; ot < 16; ot++) {
        int oc = ot * 8 + (lane & 3) * 2;
        const float* bias = (oc < 64) ? bq : bk;
        int oo = oc & 63;
        float b0 = __ldg(bias + oo), b1 = __ldg(bias + oo + 1);
        __nv_bfloat16* base = (oc < 64) ? g_q : g_k;
        uint32_t* d0 = reinterpret_cast<uint32_t*>(base + ((size_t)b * NPIX + n0 + r0) * 64 + oo);
        uint32_t* d1 = reinterpret_cast<uint32_t*>(base + ((size_t)b * NPIX + n0 + r0 + 8) * 64 + oo);
        *d0 = pack_bf2(o[ot][0] + b0, o[ot][1] + b1);
        *d1 = pack_bf2(o[ot][2] + b0, o[ot][3] + b1);
    }
}

// ---------------- proj_v: C[n(128), c(256)] = xT . Wv^T -------------------
// smem: A 2x18432 = 36864, B 2x(256x72) = 73728
__global__ __launch_bounds__(256)
void proj_v_kernel(const float* __restrict__ bv) {
    extern __shared__ char dsm[];
    const uint32_t sb = smem_u32(dsm);
    const uint32_t SA = sb, SB = sb + 36864;
    const int tid = threadIdx.x, wid = tid >> 5, lane = tid & 31;
    const int n0 = blockIdx.x * 128, ch0 = blockIdx.y * 256, b = blockIdx.z;
    const __nv_bfloat16* gA = g_xT + ((size_t)b * NPIX + n0) * CIN;
    const __nv_bfloat16* gB = g_wv + (size_t)ch0 * CIN;

    auto ldA = [&](uint32_t dst, int kk) {
        for (int i = tid; i < 1024; i += 256) {
            int r = i >> 3, s = i & 7;
            cp16(dst + r * 144 + s * 16, gA + (size_t)r * CIN + kk * 64 + s * 8);
        }
    };
    auto ldB = [&](uint32_t dst, int kk) {
        for (int i = tid; i < 2048; i += 256) {
            int r = i >> 3, s = i & 7;
            cp16(dst + r * 144 + s * 16, gB + (size_t)r * CIN + kk * 64 + s * 8);
        }
    };
    ldA(SA, 0); ldB(SB, 0); CP_COMMIT(); CP_WAIT0(); __syncthreads();

    const int ar = (lane & 7) + ((lane >> 3) & 1) * 8, ak = ((lane >> 4) & 1) * 8;
    const int bn = ((lane >> 4) & 1) * 8 + (lane & 7), bk2 = ((lane >> 3) & 1) * 8;
    float o[32][4] = {};

    for (int kk = 0; kk < 8; kk++) {
        const int buf = kk & 1;
        if (kk < 7) { ldA(SA + (buf ^ 1) * 18432, kk + 1); ldB(SB + (buf ^ 1) * 36864, kk + 1); CP_COMMIT(); }
        const uint32_t Ab = SA + buf * 18432 + (16 * wid + ar) * 144 + ak * 2;
        const uint32_t Bb = SB + buf * 36864;
        uint32_t qa[4][4];
        #pragma unroll
        for (int kc = 0; kc < 4; kc++) ldsm_x4(qa[kc], Ab + kc * 32);
        #pragma unroll
        for (int ot2 = 0; ot2 < 16; ot2++) {
            #pragma unroll
            for (int kc = 0; kc < 4; kc++) {
                uint32_t br[4];
                ldsm_x4(br, Bb + (ot2 * 16 + bn) * 144 + (kc * 16 + bk2) * 2);
                mma_bf16(o[ot2 * 2],     qa[kc], br);
                mma_bf16(o[ot2 * 2 + 1], qa[kc], br + 2);
            }
        }
        if (kk < 7) CP_WAIT0();
        __syncthreads();
    }

    const int r0 = 16 * wid + (lane >> 2);
    #pragma unroll
    for (int ot = 0; ot < 32; ot++) {
        int c = ch0 + ot * 8 + (lane & 3) * 2;
        float b0 = __ldg(bv + c), b1 = __ldg(bv + c + 1);
        uint32_t* d0 = reinterpret_cast<uint32_t*>(g_v + ((size_t)b * NPIX + n0 + r0) * CIN + c);
        uint32_t* d1 = reinterpret_cast<uint32_t*>(g_v + ((size_t)b * NPIX + n0 + r0 + 8) * CIN + c);
        *d0 = pack_bf2(o[ot][0] + b0, o[ot][1] + b1);
        *d1 = pack_bf2(o[ot][2] + b0, o[ot][3] + b1);
    }
}

// --------------------------- fused attention ------------------------------
// CTA: 128 m x 256 c-half x b. smem: Q 18432 | K 2x18432 | V 2x67584 = 190464
// Epilogue reuses smem as float epi[128][257] (131584 B).
__global__ __launch_bounds__(256, 1)
void attn_kernel(const float* __restrict__ x, float* __restrict__ out) {
    extern __shared__ char dsm[];
    const uint32_t sb = smem_u32(dsm);
    const uint32_t SQ = sb, SK = sb + 18432, SV = sb + 55296;
    const int tid = threadIdx.x, wid = tid >> 5, lane = tid & 31;
    const int m0 = blockIdx.x * 128, chalf = blockIdx.y, b = blockIdx.z;

    const __nv_bfloat16* gQ = g_q + ((size_t)b * NPIX + m0) * 64;
    const __nv_bfloat16* gK = g_k + (size_t)b * NPIX * 64;
    const __nv_bfloat16* gV = g_v + (size_t)b * NPIX * CIN + chalf * 256;

    auto ldK = [&](uint32_t dst, int jj) {
        const __nv_bfloat16* src = gK + (size_t)jj * 128 * 64;
        for (int i = tid; i < 1024; i += 256) {
            int r = i >> 3, s = i & 7;
            cp16(dst + r * 144 + s * 16, src + (size_t)r * 64 + s * 8);
        }
    };
    auto ldV = [&](uint32_t dst, int jj) {
        const __nv_bfloat16* src = gV + (size_t)jj * 128 * CIN;
        for (int i = tid; i < 4096; i += 256) {
            int r = i >> 5, s = i & 31;
            cp16(dst + r * 528 + s * 16, src + (size_t)r * CIN + s * 8);
        }
    };
    // prologue: Q + K0 + V0
    for (int i = tid; i < 1024; i += 256) {
        int r = i >> 3, s = i & 7;
        cp16(SQ + r * 144 + s * 16, gQ + (size_t)r * 64 + s * 8);
    }
    ldK(SK, 0); ldV(SV, 0);
    CP_COMMIT(); CP_WAIT0(); __syncthreads();

    // fragment lane geometry
    const int ar = (lane & 7) + ((lane >> 3) & 1) * 8, ak = ((lane >> 4) & 1) * 8;   // A / non-trans rows
    const int bn = ((lane >> 4) & 1) * 8 + (lane & 7), bk2 = ((lane >> 3) & 1) * 8;  // B non-trans
    const int vn = ((lane >> 3) & 1) * 8 + (lane & 7), vc = ((lane >> 4) & 1) * 8;   // B trans (V)

    uint32_t qa[4][4];
    {
        const uint32_t Ab = SQ + (16 * wid + ar) * 144 + ak * 2;
        #pragma unroll
        for (int kc = 0; kc < 4; kc++) ldsm_x4(qa[kc], Ab + kc * 32);
    }

    float o[32][4] = {};
    float rs0 = 0.f, rs1 = 0.f;

    for (int j = 0; j < 32; j++) {
        const int buf = j & 1;
        if (j < 31) { ldK(SK + (buf ^ 1) * 18432, j + 1); ldV(SV + (buf ^ 1) * 67584, j + 1); CP_COMMIT(); }

        // ---- S = Q . K^T, exp, pack to P fragments ----
        const uint32_t Kb = SK + buf * 18432;
        uint32_t pa[8][4];
        #pragma unroll
        for (int nt = 0; nt < 8; nt++) {
            float s0[4] = {}, s1[4] = {};
            #pragma unroll
            for (int kc = 0; kc < 4; kc++) {
                uint32_t br[4];
                ldsm_x4(br, Kb + (nt * 16 + bn) * 144 + (kc * 16 + bk2) * 2);
                mma_bf16(s0, qa[kc], br);
                mma_bf16(s1, qa[kc], br + 2);
            }
            #pragma unroll
            for (int t = 0; t < 4; t++) { s0[t] = __expf(s0[t]); s1[t] = __expf(s1[t]); }
            rs0 += s0[0] + s0[1] + s1[0] + s1[1];
            rs1 += s0[2] + s0[3] + s1[2] + s1[3];
            pa[nt][0] = pack_bf2(s0[0], s0[1]);
            pa[nt][1] = pack_bf2(s0[2], s0[3]);
            pa[nt][2] = pack_bf2(s1[0], s1[1]);
            pa[nt][3] = pack_bf2(s1[2], s1[3]);
        }

        // ---- O += P . V^T ----
        const uint32_t Vb = SV + buf * 67584;
        #pragma unroll
        for (int ct2 = 0; ct2 < 16; ct2++) {
            #pragma unroll
            for (int nt = 0; nt < 8; nt++) {
                uint32_t br[4];
                ldsm_x4t(br, Vb + (nt * 16 + vn) * 528 + (ct2 * 16 + vc) * 2);
                mma_bf16(o[ct2 * 2],     pa[nt], br);
                mma_bf16(o[ct2 * 2 + 1], pa[nt], br + 2);
            }
        }
        if (j < 31) CP_WAIT0();
        __syncthreads();
    }

    // row-sum reduce across quad lanes (lanes t%4 hold disjoint cols)
    rs0 += __shfl_xor_sync(0xffffffffu, rs0, 1);
    rs0 += __shfl_xor_sync(0xffffffffu, rs0, 2);
    rs1 += __shfl_xor_sync(0xffffffffu, rs1, 1);
    rs1 += __shfl_xor_sync(0xffffffffu, rs1, 2);
    const float inv0 = 1.0f / rs0, inv1 = 1.0f / rs1;

    // epilogue: transpose via smem (reuse), out[b][c][m] = O/sum + x
    __syncthreads();
    float* epi = reinterpret_cast<float*>(dsm);
    const int r0 = 16 * wid + (lane >> 2);
    #pragma unroll
    for (int ct = 0; ct < 32; ct++) {
        int c = ct * 8 + (lane & 3) * 2;
        epi[r0 * 257 + c]           = o[ct][0] * inv0;
        epi[r0 * 257 + c + 1]       = o[ct][1] * inv0;
        epi[(r0 + 8) * 257 + c]     = o[ct][2] * inv1;
        epi[(r0 + 8) * 257 + c + 1] = o[ct][3] * inv1;
    }
    __syncthreads();
    const float* xb = x + (size_t)b * CIN * NPIX;
    float* ob = out + (size_t)b * CIN * NPIX;
    for (int i = tid; i < 256 * 128; i += 256) {
        int c = i >> 7, m = i & 127;
        size_t gidx = (size_t)(chalf * 256 + c) * NPIX + m0 + m;
        ob[gidx] = epi[m * 257 + c] + xb[gidx];
    }
}

// ---------------------------------------------------------------------------
extern "C" void kernel_launch(void* const* d_in, const int* in_sizes, int n_in,
                              void* d_out, int out_size)
{
    const float* x  = (const float*)d_in[0];
    const float* Wq = (const float*)d_in[1];
    const float* bq = (const float*)d_in[2];
    const float* Wk = (const float*)d_in[3];
    const float* bk = (const float*)d_in[4];
    const float* Wv = (const float*)d_in[5];
    const float* bv = (const float*)d_in[6];
    float* out = (float*)d_out;

    cudaFuncSetAttribute(proj_qk_kernel, cudaFuncAttributeMaxDynamicSharedMemorySize, 73728);
    cudaFuncSetAttribute(proj_v_kernel,  cudaFuncAttributeMaxDynamicSharedMemorySize, 110592);
    cudaFuncSetAttribute(attn_kernel,    cudaFuncAttributeMaxDynamicSharedMemorySize, 190464);

    convert_w_kernel<<<1280, 256>>>(Wq, Wk, Wv);
    transpose_x_kernel<<<dim3(NPIX / 64, CIN / 64, B), 256>>>(x);
    proj_qk_kernel<<<dim3(NPIX / 128, B), 256, 73728>>>(bq, bk);
    proj_v_kernel<<<dim3(NPIX / 128, 2, B), 256, 110592>>>(bv);
    attn_kernel<<<dim3(NPIX / 128, 2, B), 256, 190464>>>(x, out);
}